// round 4
// baseline (speedup 1.0000x reference)
#include <cuda_runtime.h>
#include <cuda_bf16.h>
#include <cstdint>

#define DIM_M 8192   // B*S
#define DIM_D 2048
#define DIM_H 8192

// ---------------- scratch (static device globals; no allocation) -------------
__device__ int8_t  g_xq8[(size_t)DIM_M * DIM_D];    // int8 quantized activations
__device__ float   g_scale[DIM_M];                  // amax/127 per row (x)
__device__ int8_t  g_wg8[(size_t)DIM_H * DIM_D];    // sign(W_g) int8
__device__ int8_t  g_wu8[(size_t)DIM_H * DIM_D];    // sign(W_u) int8
__device__ int8_t  g_wd8[(size_t)DIM_D * DIM_H];    // sign(W_d) int8
__device__ float   g_pf[(size_t)DIM_M * DIM_H];     // p fp32 staging
__device__ int8_t  g_phi[(size_t)DIM_M * DIM_H];    // p int16-quant hi byte (s8)
__device__ uint8_t g_plo[(size_t)DIM_M * DIM_H];    // p int16-quant lo byte (u8)
__device__ float   g_pscale[DIM_M];                 // amax(p)/32767 per row

// ---------------- PTX helpers -------------------------------------------------
__device__ __forceinline__ uint32_t smem_u32(const void* p) {
    uint32_t a;
    asm("{ .reg .u64 t; cvta.to.shared.u64 t, %1; cvt.u32.u64 %0, t; }" : "=r"(a) : "l"(p));
    return a;
}
__device__ __forceinline__ void cp_async16(uint32_t smem, const void* gmem) {
    asm volatile("cp.async.cg.shared.global [%0], [%1], 16;\n" :: "r"(smem), "l"(gmem));
}
__device__ __forceinline__ void cp_commit() { asm volatile("cp.async.commit_group;\n"); }
template<int N> __device__ __forceinline__ void cp_wait_group() {
    asm volatile("cp.async.wait_group %0;\n" :: "n"(N));
}
__device__ __forceinline__ void ldm4(uint32_t* r, uint32_t addr) {
    asm volatile("ldmatrix.sync.aligned.m8n8.x4.shared.b16 {%0,%1,%2,%3}, [%4];"
                 : "=r"(r[0]), "=r"(r[1]), "=r"(r[2]), "=r"(r[3]) : "r"(addr));
}
__device__ __forceinline__ void mma_s8(int* d, const uint32_t* a, uint32_t b0, uint32_t b1) {
    asm volatile(
        "mma.sync.aligned.m16n8k32.row.col.s32.s8.s8.s32 "
        "{%0,%1,%2,%3}, {%4,%5,%6,%7}, {%8,%9}, {%0,%1,%2,%3};\n"
        : "+r"(d[0]), "+r"(d[1]), "+r"(d[2]), "+r"(d[3])
        : "r"(a[0]), "r"(a[1]), "r"(a[2]), "r"(a[3]), "r"(b0), "r"(b1));
}
__device__ __forceinline__ void mma_u8s8(int* d, const uint32_t* a, uint32_t b0, uint32_t b1) {
    asm volatile(
        "mma.sync.aligned.m16n8k32.row.col.s32.u8.s8.s32 "
        "{%0,%1,%2,%3}, {%4,%5,%6,%7}, {%8,%9}, {%0,%1,%2,%3};\n"
        : "+r"(d[0]), "+r"(d[1]), "+r"(d[2]), "+r"(d[3])
        : "r"(a[0]), "r"(a[1]), "r"(a[2]), "r"(a[3]), "r"(b0), "r"(b1));
}

// ---------------- misc math ---------------------------------------------------
__device__ __forceinline__ float siluf(float x) { return x / (1.0f + expf(-x)); }

__device__ __forceinline__ float block_reduce(float v, float* sm, bool ismax) {
    int lane = threadIdx.x & 31, wid = threadIdx.x >> 5;
    #pragma unroll
    for (int o = 16; o; o >>= 1) {
        float t = __shfl_xor_sync(0xffffffffu, v, o);
        v = ismax ? fmaxf(v, t) : v + t;
    }
    if (lane == 0) sm[wid] = v;
    __syncthreads();
    float out = sm[0];
    #pragma unroll
    for (int i = 1; i < 8; i++) out = ismax ? fmaxf(out, sm[i]) : out + sm[i];
    __syncthreads();
    return out;
}

// ---------------- kernel 1: layernorm + activation quant -> int8 --------------
__global__ __launch_bounds__(256) void quant_kernel(const float* __restrict__ x) {
    const int row = blockIdx.x, tid = threadIdx.x;
    const float4* xr = reinterpret_cast<const float4*>(x + (size_t)row * DIM_D);
    float4 a = xr[2 * tid], b = xr[2 * tid + 1];
    float v[8] = {a.x, a.y, a.z, a.w, b.x, b.y, b.z, b.w};

    __shared__ float sred[8];

    float s = 0.f;
    #pragma unroll
    for (int i = 0; i < 8; i++) s += v[i];
    s = block_reduce(s, sred, false);
    float mean = s * (1.0f / DIM_D);

    float q = 0.f;
    #pragma unroll
    for (int i = 0; i < 8; i++) { float d = v[i] - mean; q += d * d; }
    q = block_reduce(q, sred, false);
    float rstd = rsqrtf(q * (1.0f / DIM_D) + 1e-8f);

    float amax = 0.f;
    #pragma unroll
    for (int i = 0; i < 8; i++) amax = fmaxf(amax, fabsf((v[i] - mean) * rstd));
    amax = block_reduce(amax, sred, true);

    float sq = (amax > 0.f) ? (127.0f / amax) : 0.0f;

    uint32_t w[2] = {0, 0};
    #pragma unroll
    for (int i = 0; i < 8; i++) {
        float t = rintf((v[i] - mean) * rstd * sq);
        t = fminf(fmaxf(t, -128.f), 127.f);
        int qi = (int)t;
        w[i >> 2] |= ((uint32_t)(qi & 255)) << ((i & 3) * 8);
    }
    reinterpret_cast<uint2*>(g_xq8 + (size_t)row * DIM_D)[tid] = make_uint2(w[0], w[1]);

    if (tid == 0) g_scale[row] = amax * (1.0f / 127.0f);
}

// ---------------- kernel 2: sign -> int8 --------------------------------------
__global__ __launch_bounds__(256) void sign8_kernel(const float4* __restrict__ w,
                                                    int8_t* __restrict__ o, int n4) {
    int i = blockIdx.x * 256 + threadIdx.x;
    if (i >= n4) return;
    float4 v = w[i];
    int s0 = (v.x > 0.f) - (v.x < 0.f);
    int s1 = (v.y > 0.f) - (v.y < 0.f);
    int s2 = (v.z > 0.f) - (v.z < 0.f);
    int s3 = (v.w > 0.f) - (v.w < 0.f);
    uint32_t pk = (uint32_t)(s0 & 255) | ((uint32_t)(s1 & 255) << 8) |
                  ((uint32_t)(s2 & 255) << 16) | ((uint32_t)(s3 & 255) << 24);
    reinterpret_cast<uint32_t*>(o)[i] = pk;
}

// ---------------- kernel: quantize p (fp32) -> int16 hi/lo planes -------------
__global__ __launch_bounds__(256) void quantp_kernel() {
    const int row = blockIdx.x, tid = threadIdx.x;
    const float4* pr = reinterpret_cast<const float4*>(g_pf + (size_t)row * DIM_H);
    float4 v[8];
    #pragma unroll
    for (int i = 0; i < 8; i++) v[i] = pr[tid + i * 256];

    __shared__ float sred[8];
    float amax = 0.f;
    #pragma unroll
    for (int i = 0; i < 8; i++) {
        amax = fmaxf(amax, fmaxf(fmaxf(fabsf(v[i].x), fabsf(v[i].y)),
                                 fmaxf(fabsf(v[i].z), fabsf(v[i].w))));
    }
    amax = block_reduce(amax, sred, true);
    float s = (amax > 0.f) ? (32767.0f / amax) : 0.0f;

    uint32_t* hip = reinterpret_cast<uint32_t*>(g_phi + (size_t)row * DIM_H);
    uint32_t* lop = reinterpret_cast<uint32_t*>(g_plo + (size_t)row * DIM_H);
    #pragma unroll
    for (int i = 0; i < 8; i++) {
        float f[4] = {v[i].x, v[i].y, v[i].z, v[i].w};
        uint32_t hw = 0, lw = 0;
        #pragma unroll
        for (int e = 0; e < 4; e++) {
            float t = fminf(fmaxf(rintf(f[e] * s), -32767.f), 32767.f);
            int q = (int)t;
            hw |= ((uint32_t)((q >> 8) & 255)) << (e * 8);
            lw |= ((uint32_t)(q & 255)) << (e * 8);
        }
        hip[tid + i * 256] = hw;
        lop[tid + i * 256] = lw;
    }
    if (tid == 0) g_pscale[row] = amax * (1.0f / 32767.0f);
}

extern __shared__ __align__(128) char dsm[];

// =============================================================================
// GEMM1 (int8): per CTA M=128, N=64(g)+64(u), BK=64. 3-stage cp.async.
// smem stage (80B rows): A[128x80] @0, Bg[64x80] @10240, Bu @15360 (20480/stage)
// =============================================================================
#define G1_STAGE 20480
#define G1_SMEM  (3 * G1_STAGE)

__global__ __launch_bounds__(256, 1) void gemm1_i8() {
    const int tid = threadIdx.x, warp = tid >> 5, lane = tid & 31;
    const int bn = blockIdx.x, bm = blockIdx.y;
    const int wm = warp >> 1, wn = warp & 1;
    uint32_t sb = smem_u32(dsm);

    const int8_t* Ag  = g_xq8 + (size_t)bm * 128 * DIM_D;
    const int8_t* Bgp = g_wg8 + (size_t)bn * 64 * DIM_D;
    const int8_t* Bup = g_wu8 + (size_t)bn * 64 * DIM_D;

    int cg[2][4][4], cu[2][4][4];
    #pragma unroll
    for (int i = 0; i < 2; i++)
        #pragma unroll
        for (int j = 0; j < 4; j++)
            #pragma unroll
            for (int e = 0; e < 4; e++) { cg[i][j][e] = 0; cu[i][j][e] = 0; }

    auto load = [&](int st, int kt) {
        int k0 = kt * 64;
        uint32_t base = sb + st * G1_STAGE;
        #pragma unroll
        for (int it = 0; it < 2; it++) {
            int ch = tid + it * 256;
            int row = ch >> 2, seg = ch & 3;
            cp_async16(base + row * 80 + seg * 16, Ag + (size_t)row * DIM_D + k0 + seg * 16);
        }
        int row = tid >> 2, seg = tid & 3;
        cp_async16(base + 10240 + row * 80 + seg * 16, Bgp + (size_t)row * DIM_D + k0 + seg * 16);
        cp_async16(base + 15360 + row * 80 + seg * 16, Bup + (size_t)row * DIM_D + k0 + seg * 16);
        cp_commit();
    };

    load(0, 0); load(1, 1); load(2, 2);

    const int NCHUNK = DIM_D / 64;  // 32
    const uint32_t lrow = (lane & 15), lseg = (lane >> 4) << 4;

    for (int kt = 0; kt < NCHUNK; kt++) {
        int st = kt % 3;
        cp_wait_group<2>();
        __syncthreads();
        uint32_t base = sb + st * G1_STAGE;
        #pragma unroll
        for (int s = 0; s < 2; s++) {
            uint32_t koff = s * 32 + lseg;
            uint32_t a[2][4], bg[2][4], bu[2][4];
            #pragma unroll
            for (int i = 0; i < 2; i++)
                ldm4(a[i], base + (wm * 32 + i * 16 + lrow) * 80 + koff);
            #pragma unroll
            for (int j2 = 0; j2 < 2; j2++) {
                ldm4(bg[j2], base + 10240 + (wn * 32 + j2 * 16 + lrow) * 80 + koff);
                ldm4(bu[j2], base + 15360 + (wn * 32 + j2 * 16 + lrow) * 80 + koff);
            }
            #pragma unroll
            for (int j = 0; j < 4; j++) {
                int j2 = j >> 1, hh = j & 1;
                #pragma unroll
                for (int i = 0; i < 2; i++) {
                    mma_s8(cg[i][j], a[i], bg[j2][hh], bg[j2][2 + hh]);
                    mma_s8(cu[i][j], a[i], bu[j2][hh], bu[j2][2 + hh]);
                }
            }
        }
        __syncthreads();
        if (kt + 3 < NCHUNK) load(st, kt + 3);
        else cp_commit();
    }

    // epilogue: scale, silu, product -> fp32 p staging
    #pragma unroll
    for (int i = 0; i < 2; i++) {
        #pragma unroll
        for (int h = 0; h < 2; h++) {
            int m = bm * 128 + wm * 32 + i * 16 + (lane >> 2) + h * 8;
            float s = g_scale[m];
            size_t orow = (size_t)m * DIM_H;
            #pragma unroll
            for (int j = 0; j < 4; j++) {
                int n = bn * 64 + wn * 32 + j * 8 + (lane & 3) * 2;
                float g0 = (float)cg[i][j][h * 2 + 0] * s;
                float g1 = (float)cg[i][j][h * 2 + 1] * s;
                float u0 = (float)cu[i][j][h * 2 + 0] * s;
                float u1 = (float)cu[i][j][h * 2 + 1] * s;
                float p0 = siluf(g0) * u0;
                float p1 = siluf(g1) * u1;
                *reinterpret_cast<float2*>(g_pf + orow + n) = make_float2(p0, p1);
            }
        }
    }
}

// =============================================================================
// GEMM3 (int8 hi/lo): out = (256*hi + lo) @ wd8^T * pscale.
// CTA M=128, N=64, BK=64. 3-stage.
// smem stage (80B rows): Ahi[128x80] @0, Alo @10240, B[64x80] @20480 (25600/stage)
// =============================================================================
#define G3_STAGE 25600
#define G3_SMEM  (3 * G3_STAGE)

__global__ __launch_bounds__(256, 1) void gemm3_i8(float* __restrict__ out) {
    const int tid = threadIdx.x, warp = tid >> 5, lane = tid & 31;
    const int bn = blockIdx.x, bm = blockIdx.y;
    const int wm = warp >> 1, wn = warp & 1;
    uint32_t sb = smem_u32(dsm);

    const int8_t*  Ahi = g_phi + (size_t)bm * 128 * DIM_H;
    const uint8_t* Alo = g_plo + (size_t)bm * 128 * DIM_H;
    const int8_t*  Bw  = g_wd8 + (size_t)bn * 64 * DIM_H;

    int ch_[2][4][4], cl_[2][4][4];
    #pragma unroll
    for (int i = 0; i < 2; i++)
        #pragma unroll
        for (int j = 0; j < 4; j++)
            #pragma unroll
            for (int e = 0; e < 4; e++) { ch_[i][j][e] = 0; cl_[i][j][e] = 0; }

    auto load = [&](int st, int kt) {
        int k0 = kt * 64;
        uint32_t base = sb + st * G3_STAGE;
        #pragma unroll
        for (int it = 0; it < 2; it++) {
            int ch = tid + it * 256;
            int row = ch >> 2, seg = ch & 3;
            uint32_t d = row * 80 + seg * 16;
            size_t ga = (size_t)row * DIM_H + k0 + seg * 16;
            cp_async16(base + d,         Ahi + ga);
            cp_async16(base + 10240 + d, Alo + ga);
        }
        int row = tid >> 2, seg = tid & 3;
        cp_async16(base + 20480 + row * 80 + seg * 16, Bw + (size_t)row * DIM_H + k0 + seg * 16);
        cp_commit();
    };

    load(0, 0); load(1, 1); load(2, 2);

    const int NCHUNK = DIM_H / 64;  // 128
    const uint32_t lrow = (lane & 15), lseg = (lane >> 4) << 4;

    for (int kt = 0; kt < NCHUNK; kt++) {
        int st = kt % 3;
        cp_wait_group<2>();
        __syncthreads();
        uint32_t base = sb + st * G3_STAGE;
        #pragma unroll
        for (int s = 0; s < 2; s++) {
            uint32_t koff = s * 32 + lseg;
            uint32_t ah[2][4], al[2][4], b[2][4];
            #pragma unroll
            for (int i = 0; i < 2; i++) {
                uint32_t ra = (wm * 32 + i * 16 + lrow) * 80 + koff;
                ldm4(ah[i], base + ra);
                ldm4(al[i], base + 10240 + ra);
            }
            #pragma unroll
            for (int j2 = 0; j2 < 2; j2++)
                ldm4(b[j2], base + 20480 + (wn * 32 + j2 * 16 + lrow) * 80 + koff);
            #pragma unroll
            for (int j = 0; j < 4; j++) {
                int j2 = j >> 1, hh = j & 1;
                #pragma unroll
                for (int i = 0; i < 2; i++) {
                    mma_s8(ch_[i][j], ah[i], b[j2][hh], b[j2][2 + hh]);
                    mma_u8s8(cl_[i][j], al[i], b[j2][hh], b[j2][2 + hh]);
                }
            }
        }
        __syncthreads();
        if (kt + 3 < NCHUNK) load(st, kt + 3);
        else cp_commit();
    }

    #pragma unroll
    for (int i = 0; i < 2; i++) {
        #pragma unroll
        for (int h = 0; h < 2; h++) {
            int m = bm * 128 + wm * 32 + i * 16 + (lane >> 2) + h * 8;
            float ps = g_pscale[m];
            #pragma unroll
            for (int j = 0; j < 4; j++) {
                int n = bn * 64 + wn * 32 + j * 8 + (lane & 3) * 2;
                float v0 = (float)(ch_[i][j][h * 2 + 0] * 256 + cl_[i][j][h * 2 + 0]) * ps;
                float v1 = (float)(ch_[i][j][h * 2 + 1] * 256 + cl_[i][j][h * 2 + 1]) * ps;
                *reinterpret_cast<float2*>(out + (size_t)m * DIM_D + n) = make_float2(v0, v1);
            }
        }
    }
}

// ---------------- launch ------------------------------------------------------
extern "C" void kernel_launch(void* const* d_in, const int* in_sizes, int n_in,
                              void* d_out, int out_size) {
    const float* x  = (const float*)d_in[0];
    const float* Wg = (const float*)d_in[1];
    const float* Wu = (const float*)d_in[2];
    const float* Wd = (const float*)d_in[3];
    float* out = (float*)d_out;

    int8_t *wg_p, *wu_p, *wd_p;
    cudaGetSymbolAddress((void**)&wg_p, g_wg8);
    cudaGetSymbolAddress((void**)&wu_p, g_wu8);
    cudaGetSymbolAddress((void**)&wd_p, g_wd8);

    cudaFuncSetAttribute(gemm1_i8, cudaFuncAttributeMaxDynamicSharedMemorySize, G1_SMEM);
    cudaFuncSetAttribute(gemm3_i8, cudaFuncAttributeMaxDynamicSharedMemorySize, G3_SMEM);

    quant_kernel<<<DIM_M, 256>>>(x);

    const int n4 = DIM_H * DIM_D / 4;  // 4194304
    sign8_kernel<<<n4 / 256, 256>>>((const float4*)Wg, wg_p, n4);
    sign8_kernel<<<n4 / 256, 256>>>((const float4*)Wu, wu_p, n4);
    sign8_kernel<<<n4 / 256, 256>>>((const float4*)Wd, wd_p, n4);

    dim3 g1(DIM_H / 64, DIM_M / 128);    // (128, 64)
    gemm1_i8<<<g1, 256, G1_SMEM>>>();

    quantp_kernel<<<DIM_M, 256>>>();

    dim3 g3(DIM_D / 64, DIM_M / 128);    // (32, 64)
    gemm3_i8<<<g3, 256, G3_SMEM>>>(out);
}

// round 5
// speedup vs baseline: 2.8020x; 2.8020x over previous
#include <cuda_runtime.h>
#include <cuda_bf16.h>
#include <cuda_fp16.h>
#include <cstdint>

#define DIM_M 8192   // B*S
#define DIM_D 2048
#define DIM_H 8192

// ---------------- scratch (static device globals; no allocation) -------------
__device__ __nv_bfloat16 g_xq[(size_t)DIM_M * DIM_D];     // integer-valued quantized activations (bf16)
__device__ float         g_scale[DIM_M];                  // amax/127 per row
__device__ __nv_bfloat16 g_wg[(size_t)DIM_H * DIM_D];     // sign(W_g) bf16
__device__ __nv_bfloat16 g_wu[(size_t)DIM_H * DIM_D];     // sign(W_u) bf16
__device__ __half        g_wd[(size_t)DIM_D * DIM_H];     // sign(W_d) fp16
__device__ __half        g_p[(size_t)DIM_M * DIM_H];      // p * 2^-4, fp16

// ---------------- PTX helpers -------------------------------------------------
__device__ __forceinline__ uint32_t smem_u32(const void* p) {
    uint32_t a;
    asm("{ .reg .u64 t; cvta.to.shared.u64 t, %1; cvt.u32.u64 %0, t; }" : "=r"(a) : "l"(p));
    return a;
}
__device__ __forceinline__ void cp_async16(uint32_t smem, const void* gmem) {
    asm volatile("cp.async.cg.shared.global [%0], [%1], 16;\n" :: "r"(smem), "l"(gmem));
}
__device__ __forceinline__ void cp_commit() { asm volatile("cp.async.commit_group;\n"); }
template<int N> __device__ __forceinline__ void cp_wait_group() {
    asm volatile("cp.async.wait_group %0;\n" :: "n"(N));
}
__device__ __forceinline__ void ldm4(uint32_t* r, uint32_t addr) {
    asm volatile("ldmatrix.sync.aligned.m8n8.x4.shared.b16 {%0,%1,%2,%3}, [%4];"
                 : "=r"(r[0]), "=r"(r[1]), "=r"(r[2]), "=r"(r[3]) : "r"(addr));
}
__device__ __forceinline__ void mma_bf16(float* d, const uint32_t* a, uint32_t b0, uint32_t b1) {
    asm volatile(
        "mma.sync.aligned.m16n8k16.row.col.f32.bf16.bf16.f32 "
        "{%0,%1,%2,%3}, {%4,%5,%6,%7}, {%8,%9}, {%0,%1,%2,%3};\n"
        : "+f"(d[0]), "+f"(d[1]), "+f"(d[2]), "+f"(d[3])
        : "r"(a[0]), "r"(a[1]), "r"(a[2]), "r"(a[3]), "r"(b0), "r"(b1));
}
__device__ __forceinline__ void mma_f16(float* d, const uint32_t* a, uint32_t b0, uint32_t b1) {
    asm volatile(
        "mma.sync.aligned.m16n8k16.row.col.f32.f16.f16.f32 "
        "{%0,%1,%2,%3}, {%4,%5,%6,%7}, {%8,%9}, {%0,%1,%2,%3};\n"
        : "+f"(d[0]), "+f"(d[1]), "+f"(d[2]), "+f"(d[3])
        : "r"(a[0]), "r"(a[1]), "r"(a[2]), "r"(a[3]), "r"(b0), "r"(b1));
}

// ---------------- misc math ---------------------------------------------------
__device__ __forceinline__ float siluf(float x) { return x / (1.0f + expf(-x)); }

__device__ __forceinline__ float block_reduce(float v, float* sm, bool ismax) {
    int lane = threadIdx.x & 31, wid = threadIdx.x >> 5;
    #pragma unroll
    for (int o = 16; o; o >>= 1) {
        float t = __shfl_xor_sync(0xffffffffu, v, o);
        v = ismax ? fmaxf(v, t) : v + t;
    }
    if (lane == 0) sm[wid] = v;
    __syncthreads();
    float out = sm[0];
    #pragma unroll
    for (int i = 1; i < 8; i++) out = ismax ? fmaxf(out, sm[i]) : out + sm[i];
    __syncthreads();
    return out;
}

// ---------------- kernel 1: layernorm + activation quant (bf16 ints) ----------
__global__ __launch_bounds__(256) void quant_kernel(const float* __restrict__ x) {
    const int row = blockIdx.x, tid = threadIdx.x;
    const float4* xr = reinterpret_cast<const float4*>(x + (size_t)row * DIM_D);
    float4 a = xr[2 * tid], b = xr[2 * tid + 1];
    float v[8] = {a.x, a.y, a.z, a.w, b.x, b.y, b.z, b.w};

    __shared__ float sred[8];

    float s = 0.f;
    #pragma unroll
    for (int i = 0; i < 8; i++) s += v[i];
    s = block_reduce(s, sred, false);
    float mean = s * (1.0f / DIM_D);

    float q = 0.f;
    #pragma unroll
    for (int i = 0; i < 8; i++) { float d = v[i] - mean; q += d * d; }
    q = block_reduce(q, sred, false);
    float rstd = rsqrtf(q * (1.0f / DIM_D) + 1e-8f);

    float amax = 0.f;
    #pragma unroll
    for (int i = 0; i < 8; i++) amax = fmaxf(amax, fabsf((v[i] - mean) * rstd));
    amax = block_reduce(amax, sred, true);

    float sq = (amax > 0.f) ? (127.0f / amax) : 0.0f;

    uint32_t packed[4];
    #pragma unroll
    for (int i = 0; i < 4; i++) {
        float t0 = rintf((v[2 * i] - mean) * rstd * sq);
        float t1 = rintf((v[2 * i + 1] - mean) * rstd * sq);
        t0 = fminf(fmaxf(t0, -128.f), 127.f);
        t1 = fminf(fmaxf(t1, -128.f), 127.f);
        uint32_t lo = (uint32_t)__bfloat16_as_ushort(__float2bfloat16(t0));
        uint32_t hi = (uint32_t)__bfloat16_as_ushort(__float2bfloat16(t1));
        packed[i] = lo | (hi << 16);
    }
    reinterpret_cast<uint4*>(g_xq + (size_t)row * DIM_D)[tid] =
        make_uint4(packed[0], packed[1], packed[2], packed[3]);

    if (tid == 0) g_scale[row] = amax * (1.0f / 127.0f);
}

// ---------------- kernel 2a: sign -> bf16 -------------------------------------
__global__ __launch_bounds__(256) void signbf_kernel(const float4* __restrict__ w,
                                                     __nv_bfloat16* __restrict__ o, int n4) {
    int i = blockIdx.x * 256 + threadIdx.x;
    if (i >= n4) return;
    float4 v = w[i];
    float f0 = (v.x > 0.f) ? 1.f : ((v.x < 0.f) ? -1.f : 0.f);
    float f1 = (v.y > 0.f) ? 1.f : ((v.y < 0.f) ? -1.f : 0.f);
    float f2 = (v.z > 0.f) ? 1.f : ((v.z < 0.f) ? -1.f : 0.f);
    float f3 = (v.w > 0.f) ? 1.f : ((v.w < 0.f) ? -1.f : 0.f);
    uint32_t a0 = (uint32_t)__bfloat16_as_ushort(__float2bfloat16(f0));
    uint32_t a1 = (uint32_t)__bfloat16_as_ushort(__float2bfloat16(f1));
    uint32_t a2 = (uint32_t)__bfloat16_as_ushort(__float2bfloat16(f2));
    uint32_t a3 = (uint32_t)__bfloat16_as_ushort(__float2bfloat16(f3));
    uint2 out;
    out.x = a0 | (a1 << 16);
    out.y = a2 | (a3 << 16);
    reinterpret_cast<uint2*>(o)[i] = out;
}

// ---------------- kernel 2b: sign -> fp16 -------------------------------------
__global__ __launch_bounds__(256) void signh_kernel(const float4* __restrict__ w,
                                                    __half* __restrict__ o, int n4) {
    int i = blockIdx.x * 256 + threadIdx.x;
    if (i >= n4) return;
    float4 v = w[i];
    float f0 = (v.x > 0.f) ? 1.f : ((v.x < 0.f) ? -1.f : 0.f);
    float f1 = (v.y > 0.f) ? 1.f : ((v.y < 0.f) ? -1.f : 0.f);
    float f2 = (v.z > 0.f) ? 1.f : ((v.z < 0.f) ? -1.f : 0.f);
    float f3 = (v.w > 0.f) ? 1.f : ((v.w < 0.f) ? -1.f : 0.f);
    __half2 h0 = __floats2half2_rn(f0, f1);
    __half2 h1 = __floats2half2_rn(f2, f3);
    uint2 out;
    out.x = *reinterpret_cast<uint32_t*>(&h0);
    out.y = *reinterpret_cast<uint32_t*>(&h1);
    reinterpret_cast<uint2*>(o)[i] = out;
}

extern __shared__ __align__(128) char dsm[];

// =============================================================================
// GEMM1 (bf16): per CTA M=128, N=64(g)+64(u), BK=64. 3-stage, ldmatrix.
// smem stage (144B rows): A[128x144] @0, Bg[64x144] @18432, Bu @27648 (36864/st)
// =============================================================================
#define G1_STAGE 36864
#define G1_SMEM  (3 * G1_STAGE)

__global__ __launch_bounds__(256) void gemm1_bf() {
    const int tid = threadIdx.x, warp = tid >> 5, lane = tid & 31;
    const int bn = blockIdx.x, bm = blockIdx.y;
    const int wm = warp & 3, wn = warp >> 2;
    uint32_t sb = smem_u32(dsm);

    const __nv_bfloat16* Ag = g_xq + (size_t)bm * 128 * DIM_D;
    const __nv_bfloat16* Bg = g_wg + (size_t)bn * 64 * DIM_D;
    const __nv_bfloat16* Bu = g_wu + (size_t)bn * 64 * DIM_D;

    float cg[2][4][4], cu[2][4][4];
    #pragma unroll
    for (int i = 0; i < 2; i++)
        #pragma unroll
        for (int j = 0; j < 4; j++)
            #pragma unroll
            for (int e = 0; e < 4; e++) { cg[i][j][e] = 0.f; cu[i][j][e] = 0.f; }

    auto load = [&](int st, int kt) {
        int k0 = kt * 64;
        uint32_t base = sb + st * G1_STAGE;
        #pragma unroll
        for (int it = 0; it < 4; it++) {
            int ch = tid + it * 256;
            int row = ch >> 3, seg = ch & 7;
            cp_async16(base + row * 144 + seg * 16,
                       Ag + (size_t)row * DIM_D + k0 + seg * 8);
        }
        #pragma unroll
        for (int it = 0; it < 2; it++) {
            int ch = tid + it * 256;
            int row = ch >> 3, seg = ch & 7;
            uint32_t d = row * 144 + seg * 16;
            size_t gofs = (size_t)row * DIM_D + k0 + seg * 8;
            cp_async16(base + 18432 + d, Bg + gofs);
            cp_async16(base + 27648 + d, Bu + gofs);
        }
        cp_commit();
    };

    load(0, 0); load(1, 1); load(2, 2);

    const int NCHUNK = DIM_D / 64;  // 32
    const uint32_t lrow = (lane & 15), lseg = (lane >> 4) << 4;

    for (int kt = 0; kt < NCHUNK; kt++) {
        int st = kt % 3;
        cp_wait_group<2>();
        __syncthreads();
        uint32_t base = sb + st * G1_STAGE;
        #pragma unroll
        for (int kk = 0; kk < 4; kk++) {
            uint32_t koff = kk * 32 + lseg;
            uint32_t a[2][4], bg[2][4], bu[2][4];
            #pragma unroll
            for (int i = 0; i < 2; i++)
                ldm4(a[i], base + (wm * 32 + i * 16 + lrow) * 144 + koff);
            #pragma unroll
            for (int j2 = 0; j2 < 2; j2++) {
                uint32_t rb = (wn * 32 + j2 * 16 + lrow) * 144 + koff;
                ldm4(bg[j2], base + 18432 + rb);
                ldm4(bu[j2], base + 27648 + rb);
            }
            #pragma unroll
            for (int j = 0; j < 4; j++) {
                int j2 = j >> 1, hh = j & 1;
                #pragma unroll
                for (int i = 0; i < 2; i++) {
                    mma_bf16(cg[i][j], a[i], bg[j2][hh], bg[j2][2 + hh]);
                    mma_bf16(cu[i][j], a[i], bu[j2][hh], bu[j2][2 + hh]);
                }
            }
        }
        __syncthreads();
        if (kt + 3 < NCHUNK) load(st, kt + 3);
        else cp_commit();
    }

    // epilogue: scale, silu, product, *2^-4, fp16 store
    #pragma unroll
    for (int i = 0; i < 2; i++) {
        #pragma unroll
        for (int h = 0; h < 2; h++) {
            int m = bm * 128 + wm * 32 + i * 16 + (lane >> 2) + h * 8;
            float s = g_scale[m];
            size_t orow = (size_t)m * DIM_H;
            #pragma unroll
            for (int j = 0; j < 4; j++) {
                int n = bn * 64 + wn * 32 + j * 8 + (lane & 3) * 2;
                float g0 = cg[i][j][h * 2 + 0] * s;
                float g1 = cg[i][j][h * 2 + 1] * s;
                float u0 = cu[i][j][h * 2 + 0] * s;
                float u1 = cu[i][j][h * 2 + 1] * s;
                float p0 = siluf(g0) * u0 * 0.0625f;
                float p1 = siluf(g1) * u1 * 0.0625f;
                __half2 hp = __floats2half2_rn(p0, p1);
                *reinterpret_cast<uint32_t*>(g_p + orow + n) =
                    *reinterpret_cast<uint32_t*>(&hp);
            }
        }
    }
}

// =============================================================================
// GEMM3 (fp16): out[M,D] = 16 * (p16 @ sign(Wd)^T). CTA M=128, N=64, BK=64.
// 3-stage, ldmatrix. smem stage (144B rows): A[128x144] @0, B[64x144] @18432
// =============================================================================
#define G3_STAGE 27648
#define G3_SMEM  (3 * G3_STAGE)

__global__ __launch_bounds__(256) void gemm3_f16(float* __restrict__ out) {
    const int tid = threadIdx.x, warp = tid >> 5, lane = tid & 31;
    const int bn = blockIdx.x, bm = blockIdx.y;
    const int wm = warp & 3, wn = warp >> 2;
    uint32_t sb = smem_u32(dsm);

    const __half* Ap = g_p  + (size_t)bm * 128 * DIM_H;
    const __half* Bw = g_wd + (size_t)bn * 64 * DIM_H;

    float acc[2][4][4];
    #pragma unroll
    for (int i = 0; i < 2; i++)
        #pragma unroll
        for (int j = 0; j < 4; j++)
            #pragma unroll
            for (int e = 0; e < 4; e++) acc[i][j][e] = 0.f;

    auto load = [&](int st, int kt) {
        int k0 = kt * 64;
        uint32_t base = sb + st * G3_STAGE;
        #pragma unroll
        for (int it = 0; it < 4; it++) {
            int ch = tid + it * 256;
            int row = ch >> 3, seg = ch & 7;
            cp_async16(base + row * 144 + seg * 16,
                       Ap + (size_t)row * DIM_H + k0 + seg * 8);
        }
        #pragma unroll
        for (int it = 0; it < 2; it++) {
            int ch = tid + it * 256;
            int row = ch >> 3, seg = ch & 7;
            cp_async16(base + 18432 + row * 144 + seg * 16,
                       Bw + (size_t)row * DIM_H + k0 + seg * 8);
        }
        cp_commit();
    };

    load(0, 0); load(1, 1); load(2, 2);

    const int NCHUNK = DIM_H / 64;  // 128
    const uint32_t lrow = (lane & 15), lseg = (lane >> 4) << 4;

    for (int kt = 0; kt < NCHUNK; kt++) {
        int st = kt % 3;
        cp_wait_group<2>();
        __syncthreads();
        uint32_t base = sb + st * G3_STAGE;
        #pragma unroll
        for (int kk = 0; kk < 4; kk++) {
            uint32_t koff = kk * 32 + lseg;
            uint32_t a[2][4], b[2][4];
            #pragma unroll
            for (int i = 0; i < 2; i++)
                ldm4(a[i], base + (wm * 32 + i * 16 + lrow) * 144 + koff);
            #pragma unroll
            for (int j2 = 0; j2 < 2; j2++)
                ldm4(b[j2], base + 18432 + (wn * 32 + j2 * 16 + lrow) * 144 + koff);
            #pragma unroll
            for (int j = 0; j < 4; j++) {
                int j2 = j >> 1, hh = j & 1;
                #pragma unroll
                for (int i = 0; i < 2; i++)
                    mma_f16(acc[i][j], a[i], b[j2][hh], b[j2][2 + hh]);
            }
        }
        __syncthreads();
        if (kt + 3 < NCHUNK) load(st, kt + 3);
        else cp_commit();
    }

    #pragma unroll
    for (int i = 0; i < 2; i++) {
        #pragma unroll
        for (int h = 0; h < 2; h++) {
            int m = bm * 128 + wm * 32 + i * 16 + (lane >> 2) + h * 8;
            #pragma unroll
            for (int j = 0; j < 4; j++) {
                int n = bn * 64 + wn * 32 + j * 8 + (lane & 3) * 2;
                float2 o = make_float2(acc[i][j][h * 2 + 0] * 16.0f,
                                       acc[i][j][h * 2 + 1] * 16.0f);
                *reinterpret_cast<float2*>(out + (size_t)m * DIM_D + n) = o;
            }
        }
    }
}

// ---------------- launch ------------------------------------------------------
extern "C" void kernel_launch(void* const* d_in, const int* in_sizes, int n_in,
                              void* d_out, int out_size) {
    const float* x  = (const float*)d_in[0];
    const float* Wg = (const float*)d_in[1];
    const float* Wu = (const float*)d_in[2];
    const float* Wd = (const float*)d_in[3];
    float* out = (float*)d_out;

    __nv_bfloat16 *wg_p, *wu_p;
    __half* wd_p;
    cudaGetSymbolAddress((void**)&wg_p, g_wg);
    cudaGetSymbolAddress((void**)&wu_p, g_wu);
    cudaGetSymbolAddress((void**)&wd_p, g_wd);

    cudaFuncSetAttribute(gemm1_bf, cudaFuncAttributeMaxDynamicSharedMemorySize, G1_SMEM);
    cudaFuncSetAttribute(gemm3_f16, cudaFuncAttributeMaxDynamicSharedMemorySize, G3_SMEM);

    quant_kernel<<<DIM_M, 256>>>(x);

    const int n4 = DIM_H * DIM_D / 4;  // 4194304
    signbf_kernel<<<n4 / 256, 256>>>((const float4*)Wg, wg_p, n4);
    signbf_kernel<<<n4 / 256, 256>>>((const float4*)Wu, wu_p, n4);
    signh_kernel<<<n4 / 256, 256>>>((const float4*)Wd, wd_p, n4);

    dim3 g1(DIM_H / 64, DIM_M / 128);    // (128, 64)
    gemm1_bf<<<g1, 256, G1_SMEM>>>();

    dim3 g3(DIM_D / 64, DIM_M / 128);    // (32, 64)
    gemm3_f16<<<g3, 256, G3_SMEM>>>(out);
}

// round 6
// speedup vs baseline: 2.8580x; 1.0200x over previous
#include <cuda_runtime.h>
#include <cuda_bf16.h>
#include <cuda_fp16.h>
#include <cstdint>

#define DIM_M 8192   // B*S
#define DIM_D 2048
#define DIM_H 8192

// ---------------- scratch (static device globals; no allocation) -------------
__device__ __nv_bfloat16 g_xq[(size_t)DIM_M * DIM_D];     // integer-valued quantized activations (bf16)
__device__ float         g_scale[DIM_M];                  // amax/127 per row
__device__ __nv_bfloat16 g_wg[(size_t)DIM_H * DIM_D];     // sign(W_g) bf16
__device__ __nv_bfloat16 g_wu[(size_t)DIM_H * DIM_D];     // sign(W_u) bf16
__device__ __half        g_wd[(size_t)DIM_D * DIM_H];     // sign(W_d) fp16
__device__ __half        g_p[(size_t)DIM_M * DIM_H];      // p * 2^-4, fp16

// ---------------- PTX helpers -------------------------------------------------
__device__ __forceinline__ uint32_t smem_u32(const void* p) {
    uint32_t a;
    asm("{ .reg .u64 t; cvta.to.shared.u64 t, %1; cvt.u32.u64 %0, t; }" : "=r"(a) : "l"(p));
    return a;
}
__device__ __forceinline__ void cp_async16(uint32_t smem, const void* gmem) {
    asm volatile("cp.async.cg.shared.global [%0], [%1], 16;\n" :: "r"(smem), "l"(gmem));
}
__device__ __forceinline__ void cp_commit() { asm volatile("cp.async.commit_group;\n"); }
template<int N> __device__ __forceinline__ void cp_wait_group() {
    asm volatile("cp.async.wait_group %0;\n" :: "n"(N));
}
__device__ __forceinline__ void ldm4(uint32_t* r, uint32_t addr) {
    asm volatile("ldmatrix.sync.aligned.m8n8.x4.shared.b16 {%0,%1,%2,%3}, [%4];"
                 : "=r"(r[0]), "=r"(r[1]), "=r"(r[2]), "=r"(r[3]) : "r"(addr));
}
__device__ __forceinline__ void mma_bf16(float* d, const uint32_t* a, uint32_t b0, uint32_t b1) {
    asm volatile(
        "mma.sync.aligned.m16n8k16.row.col.f32.bf16.bf16.f32 "
        "{%0,%1,%2,%3}, {%4,%5,%6,%7}, {%8,%9}, {%0,%1,%2,%3};\n"
        : "+f"(d[0]), "+f"(d[1]), "+f"(d[2]), "+f"(d[3])
        : "r"(a[0]), "r"(a[1]), "r"(a[2]), "r"(a[3]), "r"(b0), "r"(b1));
}
__device__ __forceinline__ void mma_f16(float* d, const uint32_t* a, uint32_t b0, uint32_t b1) {
    asm volatile(
        "mma.sync.aligned.m16n8k16.row.col.f32.f16.f16.f32 "
        "{%0,%1,%2,%3}, {%4,%5,%6,%7}, {%8,%9}, {%0,%1,%2,%3};\n"
        : "+f"(d[0]), "+f"(d[1]), "+f"(d[2]), "+f"(d[3])
        : "r"(a[0]), "r"(a[1]), "r"(a[2]), "r"(a[3]), "r"(b0), "r"(b1));
}

// ---------------- misc math ---------------------------------------------------
__device__ __forceinline__ float siluf(float x) { return x / (1.0f + expf(-x)); }

__device__ __forceinline__ float block_reduce(float v, float* sm, bool ismax) {
    int lane = threadIdx.x & 31, wid = threadIdx.x >> 5;
    #pragma unroll
    for (int o = 16; o; o >>= 1) {
        float t = __shfl_xor_sync(0xffffffffu, v, o);
        v = ismax ? fmaxf(v, t) : v + t;
    }
    if (lane == 0) sm[wid] = v;
    __syncthreads();
    float out = sm[0];
    #pragma unroll
    for (int i = 1; i < 8; i++) out = ismax ? fmaxf(out, sm[i]) : out + sm[i];
    __syncthreads();
    return out;
}

// ---------------- kernel 1: layernorm + activation quant (bf16 ints) ----------
__global__ __launch_bounds__(256) void quant_kernel(const float* __restrict__ x) {
    const int row = blockIdx.x, tid = threadIdx.x;
    const float4* xr = reinterpret_cast<const float4*>(x + (size_t)row * DIM_D);
    float4 a = xr[2 * tid], b = xr[2 * tid + 1];
    float v[8] = {a.x, a.y, a.z, a.w, b.x, b.y, b.z, b.w};

    __shared__ float sred[8];

    float s = 0.f;
    #pragma unroll
    for (int i = 0; i < 8; i++) s += v[i];
    s = block_reduce(s, sred, false);
    float mean = s * (1.0f / DIM_D);

    float q = 0.f;
    #pragma unroll
    for (int i = 0; i < 8; i++) { float d = v[i] - mean; q += d * d; }
    q = block_reduce(q, sred, false);
    float rstd = rsqrtf(q * (1.0f / DIM_D) + 1e-8f);

    float amax = 0.f;
    #pragma unroll
    for (int i = 0; i < 8; i++) amax = fmaxf(amax, fabsf((v[i] - mean) * rstd));
    amax = block_reduce(amax, sred, true);

    float sq = (amax > 0.f) ? (127.0f / amax) : 0.0f;

    uint32_t packed[4];
    #pragma unroll
    for (int i = 0; i < 4; i++) {
        float t0 = rintf((v[2 * i] - mean) * rstd * sq);
        float t1 = rintf((v[2 * i + 1] - mean) * rstd * sq);
        t0 = fminf(fmaxf(t0, -128.f), 127.f);
        t1 = fminf(fmaxf(t1, -128.f), 127.f);
        uint32_t lo = (uint32_t)__bfloat16_as_ushort(__float2bfloat16(t0));
        uint32_t hi = (uint32_t)__bfloat16_as_ushort(__float2bfloat16(t1));
        packed[i] = lo | (hi << 16);
    }
    reinterpret_cast<uint4*>(g_xq + (size_t)row * DIM_D)[tid] =
        make_uint4(packed[0], packed[1], packed[2], packed[3]);

    if (tid == 0) g_scale[row] = amax * (1.0f / 127.0f);
}

// ---------------- kernel 2: fused sign conversion (Wg,Wu -> bf16; Wd -> fp16) --
__global__ __launch_bounds__(256) void sign_fused_kernel(
        const float4* __restrict__ wg, const float4* __restrict__ wu,
        const float4* __restrict__ wd, int n4) {
    int gi = blockIdx.x * 256 + threadIdx.x;
    int which = gi / n4;          // 0: Wg, 1: Wu, 2: Wd
    int i = gi - which * n4;
    if (which < 2) {
        const float4 v = (which == 0) ? wg[i] : wu[i];
        __nv_bfloat16* o = (which == 0) ? g_wg : g_wu;
        // sign -> bf16 (+1 = 0x3F80, -1 = 0xBF80, 0 = 0)
        float f0 = (v.x > 0.f) ? 1.f : ((v.x < 0.f) ? -1.f : 0.f);
        float f1 = (v.y > 0.f) ? 1.f : ((v.y < 0.f) ? -1.f : 0.f);
        float f2 = (v.z > 0.f) ? 1.f : ((v.z < 0.f) ? -1.f : 0.f);
        float f3 = (v.w > 0.f) ? 1.f : ((v.w < 0.f) ? -1.f : 0.f);
        uint32_t a0 = (uint32_t)__bfloat16_as_ushort(__float2bfloat16(f0));
        uint32_t a1 = (uint32_t)__bfloat16_as_ushort(__float2bfloat16(f1));
        uint32_t a2 = (uint32_t)__bfloat16_as_ushort(__float2bfloat16(f2));
        uint32_t a3 = (uint32_t)__bfloat16_as_ushort(__float2bfloat16(f3));
        uint2 out;
        out.x = a0 | (a1 << 16);
        out.y = a2 | (a3 << 16);
        reinterpret_cast<uint2*>(o)[i] = out;
    } else {
        const float4 v = wd[i];
        float f0 = (v.x > 0.f) ? 1.f : ((v.x < 0.f) ? -1.f : 0.f);
        float f1 = (v.y > 0.f) ? 1.f : ((v.y < 0.f) ? -1.f : 0.f);
        float f2 = (v.z > 0.f) ? 1.f : ((v.z < 0.f) ? -1.f : 0.f);
        float f3 = (v.w > 0.f) ? 1.f : ((v.w < 0.f) ? -1.f : 0.f);
        __half2 h0 = __floats2half2_rn(f0, f1);
        __half2 h1 = __floats2half2_rn(f2, f3);
        uint2 out;
        out.x = *reinterpret_cast<uint32_t*>(&h0);
        out.y = *reinterpret_cast<uint32_t*>(&h1);
        reinterpret_cast<uint2*>(g_wd)[i] = out;
    }
}

extern __shared__ __align__(128) char dsm[];

// =============================================================================
// GEMM1 (bf16): per CTA M=128, N=64(g)+64(u), BK=64. 3-stage, ldmatrix,
// single __syncthreads per iteration (CUTLASS multistage ordering).
// smem stage (144B rows): A[128x144] @0, Bg[64x144] @18432, Bu @27648 (36864/st)
// =============================================================================
#define G1_STAGE 36864
#define G1_SMEM  (3 * G1_STAGE)

__global__ __launch_bounds__(256) void gemm1_bf() {
    const int tid = threadIdx.x, warp = tid >> 5, lane = tid & 31;
    const int bn = blockIdx.x, bm = blockIdx.y;
    const int wm = warp & 3, wn = warp >> 2;
    uint32_t sb = smem_u32(dsm);

    const __nv_bfloat16* Ag = g_xq + (size_t)bm * 128 * DIM_D;
    const __nv_bfloat16* Bg = g_wg + (size_t)bn * 64 * DIM_D;
    const __nv_bfloat16* Bu = g_wu + (size_t)bn * 64 * DIM_D;

    float cg[2][4][4], cu[2][4][4];
    #pragma unroll
    for (int i = 0; i < 2; i++)
        #pragma unroll
        for (int j = 0; j < 4; j++)
            #pragma unroll
            for (int e = 0; e < 4; e++) { cg[i][j][e] = 0.f; cu[i][j][e] = 0.f; }

    auto load = [&](int st, int kt) {
        int k0 = kt * 64;
        uint32_t base = sb + st * G1_STAGE;
        #pragma unroll
        for (int it = 0; it < 4; it++) {
            int ch = tid + it * 256;
            int row = ch >> 3, seg = ch & 7;
            cp_async16(base + row * 144 + seg * 16,
                       Ag + (size_t)row * DIM_D + k0 + seg * 8);
        }
        #pragma unroll
        for (int it = 0; it < 2; it++) {
            int ch = tid + it * 256;
            int row = ch >> 3, seg = ch & 7;
            uint32_t d = row * 144 + seg * 16;
            size_t gofs = (size_t)row * DIM_D + k0 + seg * 8;
            cp_async16(base + 18432 + d, Bg + gofs);
            cp_async16(base + 27648 + d, Bu + gofs);
        }
        cp_commit();
    };

    load(0, 0); load(1, 1);   // 2 prologue stages; stage 2 filled at kt=0

    const int NCHUNK = DIM_D / 64;  // 32
    const uint32_t lrow = (lane & 15), lseg = (lane >> 4) << 4;

    for (int kt = 0; kt < NCHUNK; kt++) {
        int st = kt % 3;
        cp_wait_group<1>();
        __syncthreads();
        if (kt + 2 < NCHUNK) load((kt + 2) % 3, kt + 2);
        uint32_t base = sb + st * G1_STAGE;
        #pragma unroll
        for (int kk = 0; kk < 4; kk++) {
            uint32_t koff = kk * 32 + lseg;
            uint32_t a[2][4], bg[2][4], bu[2][4];
            #pragma unroll
            for (int i = 0; i < 2; i++)
                ldm4(a[i], base + (wm * 32 + i * 16 + lrow) * 144 + koff);
            #pragma unroll
            for (int j2 = 0; j2 < 2; j2++) {
                uint32_t rb = (wn * 32 + j2 * 16 + lrow) * 144 + koff;
                ldm4(bg[j2], base + 18432 + rb);
                ldm4(bu[j2], base + 27648 + rb);
            }
            #pragma unroll
            for (int j = 0; j < 4; j++) {
                int j2 = j >> 1, hh = j & 1;
                #pragma unroll
                for (int i = 0; i < 2; i++) {
                    mma_bf16(cg[i][j], a[i], bg[j2][hh], bg[j2][2 + hh]);
                    mma_bf16(cu[i][j], a[i], bu[j2][hh], bu[j2][2 + hh]);
                }
            }
        }
    }

    // epilogue: scale, silu, product, *2^-4, fp16 store
    #pragma unroll
    for (int i = 0; i < 2; i++) {
        #pragma unroll
        for (int h = 0; h < 2; h++) {
            int m = bm * 128 + wm * 32 + i * 16 + (lane >> 2) + h * 8;
            float s = g_scale[m];
            size_t orow = (size_t)m * DIM_H;
            #pragma unroll
            for (int j = 0; j < 4; j++) {
                int n = bn * 64 + wn * 32 + j * 8 + (lane & 3) * 2;
                float g0 = cg[i][j][h * 2 + 0] * s;
                float g1 = cg[i][j][h * 2 + 1] * s;
                float u0 = cu[i][j][h * 2 + 0] * s;
                float u1 = cu[i][j][h * 2 + 1] * s;
                float p0 = siluf(g0) * u0 * 0.0625f;
                float p1 = siluf(g1) * u1 * 0.0625f;
                __half2 hp = __floats2half2_rn(p0, p1);
                *reinterpret_cast<uint32_t*>(g_p + orow + n) =
                    *reinterpret_cast<uint32_t*>(&hp);
            }
        }
    }
}

// =============================================================================
// GEMM3 (fp16): out[M,D] = 16 * (p16 @ sign(Wd)^T). CTA M=128, N=64, BK=64.
// 3-stage, ldmatrix, single sync/iter.
// smem stage (144B rows): A[128x144] @0, B[64x144] @18432  (27648/stage)
// =============================================================================
#define G3_STAGE 27648
#define G3_SMEM  (3 * G3_STAGE)

__global__ __launch_bounds__(256) void gemm3_f16(float* __restrict__ out) {
    const int tid = threadIdx.x, warp = tid >> 5, lane = tid & 31;
    const int bn = blockIdx.x, bm = blockIdx.y;
    const int wm = warp & 3, wn = warp >> 2;
    uint32_t sb = smem_u32(dsm);

    const __half* Ap = g_p  + (size_t)bm * 128 * DIM_H;
    const __half* Bw = g_wd + (size_t)bn * 64 * DIM_H;

    float acc[2][4][4];
    #pragma unroll
    for (int i = 0; i < 2; i++)
        #pragma unroll
        for (int j = 0; j < 4; j++)
            #pragma unroll
            for (int e = 0; e < 4; e++) acc[i][j][e] = 0.f;

    auto load = [&](int st, int kt) {
        int k0 = kt * 64;
        uint32_t base = sb + st * G3_STAGE;
        #pragma unroll
        for (int it = 0; it < 4; it++) {
            int ch = tid + it * 256;
            int row = ch >> 3, seg = ch & 7;
            cp_async16(base + row * 144 + seg * 16,
                       Ap + (size_t)row * DIM_H + k0 + seg * 8);
        }
        #pragma unroll
        for (int it = 0; it < 2; it++) {
            int ch = tid + it * 256;
            int row = ch >> 3, seg = ch & 7;
            cp_async16(base + 18432 + row * 144 + seg * 16,
                       Bw + (size_t)row * DIM_H + k0 + seg * 8);
        }
        cp_commit();
    };

    load(0, 0); load(1, 1);

    const int NCHUNK = DIM_H / 64;  // 128
    const uint32_t lrow = (lane & 15), lseg = (lane >> 4) << 4;

    for (int kt = 0; kt < NCHUNK; kt++) {
        int st = kt % 3;
        cp_wait_group<1>();
        __syncthreads();
        if (kt + 2 < NCHUNK) load((kt + 2) % 3, kt + 2);
        uint32_t base = sb + st * G3_STAGE;
        #pragma unroll
        for (int kk = 0; kk < 4; kk++) {
            uint32_t koff = kk * 32 + lseg;
            uint32_t a[2][4], b[2][4];
            #pragma unroll
            for (int i = 0; i < 2; i++)
                ldm4(a[i], base + (wm * 32 + i * 16 + lrow) * 144 + koff);
            #pragma unroll
            for (int j2 = 0; j2 < 2; j2++)
                ldm4(b[j2], base + 18432 + (wn * 32 + j2 * 16 + lrow) * 144 + koff);
            #pragma unroll
            for (int j = 0; j < 4; j++) {
                int j2 = j >> 1, hh = j & 1;
                #pragma unroll
                for (int i = 0; i < 2; i++)
                    mma_f16(acc[i][j], a[i], b[j2][hh], b[j2][2 + hh]);
            }
        }
    }

    #pragma unroll
    for (int i = 0; i < 2; i++) {
        #pragma unroll
        for (int h = 0; h < 2; h++) {
            int m = bm * 128 + wm * 32 + i * 16 + (lane >> 2) + h * 8;
            #pragma unroll
            for (int j = 0; j < 4; j++) {
                int n = bn * 64 + wn * 32 + j * 8 + (lane & 3) * 2;
                float2 o = make_float2(acc[i][j][h * 2 + 0] * 16.0f,
                                       acc[i][j][h * 2 + 1] * 16.0f);
                *reinterpret_cast<float2*>(out + (size_t)m * DIM_D + n) = o;
            }
        }
    }
}

// ---------------- launch ------------------------------------------------------
extern "C" void kernel_launch(void* const* d_in, const int* in_sizes, int n_in,
                              void* d_out, int out_size) {
    const float* x  = (const float*)d_in[0];
    const float* Wg = (const float*)d_in[1];
    const float* Wu = (const float*)d_in[2];
    const float* Wd = (const float*)d_in[3];
    float* out = (float*)d_out;

    cudaFuncSetAttribute(gemm1_bf, cudaFuncAttributeMaxDynamicSharedMemorySize, G1_SMEM);
    cudaFuncSetAttribute(gemm3_f16, cudaFuncAttributeMaxDynamicSharedMemorySize, G3_SMEM);

    quant_kernel<<<DIM_M, 256>>>(x);

    const int n4 = DIM_H * DIM_D / 4;  // 4194304
    sign_fused_kernel<<<3 * n4 / 256, 256>>>((const float4*)Wg, (const float4*)Wu,
                                             (const float4*)Wd, n4);

    dim3 g1(DIM_H / 64, DIM_M / 128);    // (128, 64)
    gemm1_bf<<<g1, 256, G1_SMEM>>>();

    dim3 g3(DIM_D / 64, DIM_M / 128);    // (32, 64)
    gemm3_f16<<<g3, 256, G3_SMEM>>>(out);
}

// round 7
// speedup vs baseline: 3.0338x; 1.0615x over previous
#include <cuda_runtime.h>
#include <cuda_bf16.h>
#include <cuda_fp16.h>
#include <cstdint>

#define DIM_M 8192   // B*S
#define DIM_D 2048
#define DIM_H 8192

// ---------------- scratch (static device globals; no allocation) -------------
__device__ __nv_bfloat16 g_xq[(size_t)DIM_M * DIM_D];     // integer-valued quantized activations (bf16)
__device__ float         g_scale[DIM_M];                  // amax/127 per row
__device__ __nv_bfloat16 g_wg[(size_t)DIM_H * DIM_D];     // sign(W_g) bf16
__device__ __nv_bfloat16 g_wu[(size_t)DIM_H * DIM_D];     // sign(W_u) bf16
__device__ __half        g_wd[(size_t)DIM_D * DIM_H];     // sign(W_d) fp16
__device__ __half        g_p[(size_t)DIM_M * DIM_H];      // p * 2^-4, fp16

// ---------------- PTX helpers -------------------------------------------------
__device__ __forceinline__ uint32_t smem_u32(const void* p) {
    uint32_t a;
    asm("{ .reg .u64 t; cvta.to.shared.u64 t, %1; cvt.u32.u64 %0, t; }" : "=r"(a) : "l"(p));
    return a;
}
__device__ __forceinline__ void cp_async16(uint32_t smem, const void* gmem) {
    asm volatile("cp.async.cg.shared.global [%0], [%1], 16;\n" :: "r"(smem), "l"(gmem));
}
__device__ __forceinline__ void cp_commit() { asm volatile("cp.async.commit_group;\n"); }
template<int N> __device__ __forceinline__ void cp_wait_group() {
    asm volatile("cp.async.wait_group %0;\n" :: "n"(N));
}
__device__ __forceinline__ void ldm4(uint32_t* r, uint32_t addr) {
    asm volatile("ldmatrix.sync.aligned.m8n8.x4.shared.b16 {%0,%1,%2,%3}, [%4];"
                 : "=r"(r[0]), "=r"(r[1]), "=r"(r[2]), "=r"(r[3]) : "r"(addr));
}
__device__ __forceinline__ void mma_bf16(float* d, const uint32_t* a, uint32_t b0, uint32_t b1) {
    asm volatile(
        "mma.sync.aligned.m16n8k16.row.col.f32.bf16.bf16.f32 "
        "{%0,%1,%2,%3}, {%4,%5,%6,%7}, {%8,%9}, {%0,%1,%2,%3};\n"
        : "+f"(d[0]), "+f"(d[1]), "+f"(d[2]), "+f"(d[3])
        : "r"(a[0]), "r"(a[1]), "r"(a[2]), "r"(a[3]), "r"(b0), "r"(b1));
}
__device__ __forceinline__ void mma_f16(float* d, const uint32_t* a, uint32_t b0, uint32_t b1) {
    asm volatile(
        "mma.sync.aligned.m16n8k16.row.col.f32.f16.f16.f32 "
        "{%0,%1,%2,%3}, {%4,%5,%6,%7}, {%8,%9}, {%0,%1,%2,%3};\n"
        : "+f"(d[0]), "+f"(d[1]), "+f"(d[2]), "+f"(d[3])
        : "r"(a[0]), "r"(a[1]), "r"(a[2]), "r"(a[3]), "r"(b0), "r"(b1));
}

// ---------------- misc math ---------------------------------------------------
__device__ __forceinline__ float siluf(float x) { return x / (1.0f + expf(-x)); }

__device__ __forceinline__ float block_reduce(float v, float* sm, bool ismax) {
    int lane = threadIdx.x & 31, wid = threadIdx.x >> 5;
    #pragma unroll
    for (int o = 16; o; o >>= 1) {
        float t = __shfl_xor_sync(0xffffffffu, v, o);
        v = ismax ? fmaxf(v, t) : v + t;
    }
    if (lane == 0) sm[wid] = v;
    __syncthreads();
    float out = sm[0];
    #pragma unroll
    for (int i = 1; i < 8; i++) out = ismax ? fmaxf(out, sm[i]) : out + sm[i];
    __syncthreads();
    return out;
}

// ---------------- kernel 1: layernorm + activation quant (bf16 ints) ----------
__global__ __launch_bounds__(256) void quant_kernel(const float* __restrict__ x) {
    const int row = blockIdx.x, tid = threadIdx.x;
    const float4* xr = reinterpret_cast<const float4*>(x + (size_t)row * DIM_D);
    float4 a = xr[2 * tid], b = xr[2 * tid + 1];
    float v[8] = {a.x, a.y, a.z, a.w, b.x, b.y, b.z, b.w};

    __shared__ float sred[8];

    float s = 0.f;
    #pragma unroll
    for (int i = 0; i < 8; i++) s += v[i];
    s = block_reduce(s, sred, false);
    float mean = s * (1.0f / DIM_D);

    float q = 0.f;
    #pragma unroll
    for (int i = 0; i < 8; i++) { float d = v[i] - mean; q += d * d; }
    q = block_reduce(q, sred, false);
    float rstd = rsqrtf(q * (1.0f / DIM_D) + 1e-8f);

    float amax = 0.f;
    #pragma unroll
    for (int i = 0; i < 8; i++) amax = fmaxf(amax, fabsf((v[i] - mean) * rstd));
    amax = block_reduce(amax, sred, true);

    float sq = (amax > 0.f) ? (127.0f / amax) : 0.0f;

    uint32_t packed[4];
    #pragma unroll
    for (int i = 0; i < 4; i++) {
        float t0 = rintf((v[2 * i] - mean) * rstd * sq);
        float t1 = rintf((v[2 * i + 1] - mean) * rstd * sq);
        t0 = fminf(fmaxf(t0, -128.f), 127.f);
        t1 = fminf(fmaxf(t1, -128.f), 127.f);
        uint32_t lo = (uint32_t)__bfloat16_as_ushort(__float2bfloat16(t0));
        uint32_t hi = (uint32_t)__bfloat16_as_ushort(__float2bfloat16(t1));
        packed[i] = lo | (hi << 16);
    }
    reinterpret_cast<uint4*>(g_xq + (size_t)row * DIM_D)[tid] =
        make_uint4(packed[0], packed[1], packed[2], packed[3]);

    if (tid == 0) g_scale[row] = amax * (1.0f / 127.0f);
}

// ---------------- kernel 2: fused sign conversion (Wg,Wu -> bf16; Wd -> fp16) --
__global__ __launch_bounds__(256) void sign_fused_kernel(
        const float4* __restrict__ wg, const float4* __restrict__ wu,
        const float4* __restrict__ wd, int n4) {
    int gi = blockIdx.x * 256 + threadIdx.x;
    int which = gi / n4;          // 0: Wg, 1: Wu, 2: Wd
    int i = gi - which * n4;
    if (which < 2) {
        const float4 v = (which == 0) ? wg[i] : wu[i];
        __nv_bfloat16* o = (which == 0) ? g_wg : g_wu;
        float f0 = (v.x > 0.f) ? 1.f : ((v.x < 0.f) ? -1.f : 0.f);
        float f1 = (v.y > 0.f) ? 1.f : ((v.y < 0.f) ? -1.f : 0.f);
        float f2 = (v.z > 0.f) ? 1.f : ((v.z < 0.f) ? -1.f : 0.f);
        float f3 = (v.w > 0.f) ? 1.f : ((v.w < 0.f) ? -1.f : 0.f);
        uint32_t a0 = (uint32_t)__bfloat16_as_ushort(__float2bfloat16(f0));
        uint32_t a1 = (uint32_t)__bfloat16_as_ushort(__float2bfloat16(f1));
        uint32_t a2 = (uint32_t)__bfloat16_as_ushort(__float2bfloat16(f2));
        uint32_t a3 = (uint32_t)__bfloat16_as_ushort(__float2bfloat16(f3));
        uint2 out;
        out.x = a0 | (a1 << 16);
        out.y = a2 | (a3 << 16);
        reinterpret_cast<uint2*>(o)[i] = out;
    } else {
        const float4 v = wd[i];
        float f0 = (v.x > 0.f) ? 1.f : ((v.x < 0.f) ? -1.f : 0.f);
        float f1 = (v.y > 0.f) ? 1.f : ((v.y < 0.f) ? -1.f : 0.f);
        float f2 = (v.z > 0.f) ? 1.f : ((v.z < 0.f) ? -1.f : 0.f);
        float f3 = (v.w > 0.f) ? 1.f : ((v.w < 0.f) ? -1.f : 0.f);
        __half2 h0 = __floats2half2_rn(f0, f1);
        __half2 h1 = __floats2half2_rn(f2, f3);
        uint2 out;
        out.x = *reinterpret_cast<uint32_t*>(&h0);
        out.y = *reinterpret_cast<uint32_t*>(&h1);
        reinterpret_cast<uint2*>(g_wd)[i] = out;
    }
}

extern __shared__ __align__(128) char dsm[];

// =============================================================================
// GEMM1 (bf16): per CTA M=128, N=64(g)+64(u), BK=64. 3-stage, ldmatrix,
// single __syncthreads per iteration.
// smem stage (144B rows): A[128x144] @0, Bg[64x144] @18432, Bu @27648 (36864/st)
// =============================================================================
#define G1_STAGE 36864
#define G1_SMEM  (3 * G1_STAGE)

__global__ __launch_bounds__(256) void gemm1_bf() {
    const int tid = threadIdx.x, warp = tid >> 5, lane = tid & 31;
    const int bn = blockIdx.x, bm = blockIdx.y;
    const int wm = warp & 3, wn = warp >> 2;
    uint32_t sb = smem_u32(dsm);

    const __nv_bfloat16* Ag = g_xq + (size_t)bm * 128 * DIM_D;
    const __nv_bfloat16* Bg = g_wg + (size_t)bn * 64 * DIM_D;
    const __nv_bfloat16* Bu = g_wu + (size_t)bn * 64 * DIM_D;

    float cg[2][4][4], cu[2][4][4];
    #pragma unroll
    for (int i = 0; i < 2; i++)
        #pragma unroll
        for (int j = 0; j < 4; j++)
            #pragma unroll
            for (int e = 0; e < 4; e++) { cg[i][j][e] = 0.f; cu[i][j][e] = 0.f; }

    auto load = [&](int st, int kt) {
        int k0 = kt * 64;
        uint32_t base = sb + st * G1_STAGE;
        #pragma unroll
        for (int it = 0; it < 4; it++) {
            int ch = tid + it * 256;
            int row = ch >> 3, seg = ch & 7;
            cp_async16(base + row * 144 + seg * 16,
                       Ag + (size_t)row * DIM_D + k0 + seg * 8);
        }
        #pragma unroll
        for (int it = 0; it < 2; it++) {
            int ch = tid + it * 256;
            int row = ch >> 3, seg = ch & 7;
            uint32_t d = row * 144 + seg * 16;
            size_t gofs = (size_t)row * DIM_D + k0 + seg * 8;
            cp_async16(base + 18432 + d, Bg + gofs);
            cp_async16(base + 27648 + d, Bu + gofs);
        }
        cp_commit();
    };

    load(0, 0); load(1, 1);

    const int NCHUNK = DIM_D / 64;  // 32
    const uint32_t lrow = (lane & 15), lseg = (lane >> 4) << 4;

    for (int kt = 0; kt < NCHUNK; kt++) {
        int st = kt % 3;
        cp_wait_group<1>();
        __syncthreads();
        if (kt + 2 < NCHUNK) load((kt + 2) % 3, kt + 2);
        uint32_t base = sb + st * G1_STAGE;
        #pragma unroll
        for (int kk = 0; kk < 4; kk++) {
            uint32_t koff = kk * 32 + lseg;
            uint32_t a[2][4], bg[2][4], bu[2][4];
            #pragma unroll
            for (int i = 0; i < 2; i++)
                ldm4(a[i], base + (wm * 32 + i * 16 + lrow) * 144 + koff);
            #pragma unroll
            for (int j2 = 0; j2 < 2; j2++) {
                uint32_t rb = (wn * 32 + j2 * 16 + lrow) * 144 + koff;
                ldm4(bg[j2], base + 18432 + rb);
                ldm4(bu[j2], base + 27648 + rb);
            }
            #pragma unroll
            for (int j = 0; j < 4; j++) {
                int j2 = j >> 1, hh = j & 1;
                #pragma unroll
                for (int i = 0; i < 2; i++) {
                    mma_bf16(cg[i][j], a[i], bg[j2][hh], bg[j2][2 + hh]);
                    mma_bf16(cu[i][j], a[i], bu[j2][hh], bu[j2][2 + hh]);
                }
            }
        }
    }

    // epilogue: scale, silu, product, *2^-4, fp16 store
    #pragma unroll
    for (int i = 0; i < 2; i++) {
        #pragma unroll
        for (int h = 0; h < 2; h++) {
            int m = bm * 128 + wm * 32 + i * 16 + (lane >> 2) + h * 8;
            float s = g_scale[m];
            size_t orow = (size_t)m * DIM_H;
            #pragma unroll
            for (int j = 0; j < 4; j++) {
                int n = bn * 64 + wn * 32 + j * 8 + (lane & 3) * 2;
                float g0 = cg[i][j][h * 2 + 0] * s;
                float g1 = cg[i][j][h * 2 + 1] * s;
                float u0 = cu[i][j][h * 2 + 0] * s;
                float u1 = cu[i][j][h * 2 + 1] * s;
                float p0 = siluf(g0) * u0 * 0.0625f;
                float p1 = siluf(g1) * u1 * 0.0625f;
                __half2 hp = __floats2half2_rn(p0, p1);
                *reinterpret_cast<uint32_t*>(g_p + orow + n) =
                    *reinterpret_cast<uint32_t*>(&hp);
            }
        }
    }
}

// =============================================================================
// GEMM3 (fp16): out[M,D] = 16 * (p16 @ sign(Wd)^T). CTA M=128, N=128 (two
// 64-col halves sharing A fragments -> 21.3 FLOP/B smem reads). BK=64,
// 3-stage, ldmatrix, single sync/iter. Structure mirrors gemm1_bf.
// smem stage (144B rows): A[128x144] @0, B0[64x144] @18432, B1 @27648 (36864/st)
// =============================================================================
#define G3_STAGE 36864
#define G3_SMEM  (3 * G3_STAGE)

__global__ __launch_bounds__(256) void gemm3_f16(float* __restrict__ out) {
    const int tid = threadIdx.x, warp = tid >> 5, lane = tid & 31;
    const int bn = blockIdx.x, bm = blockIdx.y;
    const int wm = warp & 3, wn = warp >> 2;
    uint32_t sb = smem_u32(dsm);

    const __half* Ap = g_p  + (size_t)bm * 128 * DIM_H;
    const __half* B0 = g_wd + (size_t)bn * 128 * DIM_H;            // rows [0,64)
    const __half* B1 = B0 + (size_t)64 * DIM_H;                    // rows [64,128)

    float c0[2][4][4], c1[2][4][4];
    #pragma unroll
    for (int i = 0; i < 2; i++)
        #pragma unroll
        for (int j = 0; j < 4; j++)
            #pragma unroll
            for (int e = 0; e < 4; e++) { c0[i][j][e] = 0.f; c1[i][j][e] = 0.f; }

    auto load = [&](int st, int kt) {
        int k0 = kt * 64;
        uint32_t base = sb + st * G3_STAGE;
        #pragma unroll
        for (int it = 0; it < 4; it++) {
            int ch = tid + it * 256;
            int row = ch >> 3, seg = ch & 7;
            cp_async16(base + row * 144 + seg * 16,
                       Ap + (size_t)row * DIM_H + k0 + seg * 8);
        }
        #pragma unroll
        for (int it = 0; it < 2; it++) {
            int ch = tid + it * 256;
            int row = ch >> 3, seg = ch & 7;
            uint32_t d = row * 144 + seg * 16;
            size_t gofs = (size_t)row * DIM_H + k0 + seg * 8;
            cp_async16(base + 18432 + d, B0 + gofs);
            cp_async16(base + 27648 + d, B1 + gofs);
        }
        cp_commit();
    };

    load(0, 0); load(1, 1);

    const int NCHUNK = DIM_H / 64;  // 128
    const uint32_t lrow = (lane & 15), lseg = (lane >> 4) << 4;

    for (int kt = 0; kt < NCHUNK; kt++) {
        int st = kt % 3;
        cp_wait_group<1>();
        __syncthreads();
        if (kt + 2 < NCHUNK) load((kt + 2) % 3, kt + 2);
        uint32_t base = sb + st * G3_STAGE;
        #pragma unroll
        for (int kk = 0; kk < 4; kk++) {
            uint32_t koff = kk * 32 + lseg;
            uint32_t a[2][4], b0[2][4], b1[2][4];
            #pragma unroll
            for (int i = 0; i < 2; i++)
                ldm4(a[i], base + (wm * 32 + i * 16 + lrow) * 144 + koff);
            #pragma unroll
            for (int j2 = 0; j2 < 2; j2++) {
                uint32_t rb = (wn * 32 + j2 * 16 + lrow) * 144 + koff;
                ldm4(b0[j2], base + 18432 + rb);
                ldm4(b1[j2], base + 27648 + rb);
            }
            #pragma unroll
            for (int j = 0; j < 4; j++) {
                int j2 = j >> 1, hh = j & 1;
                #pragma unroll
                for (int i = 0; i < 2; i++) {
                    mma_f16(c0[i][j], a[i], b0[j2][hh], b0[j2][2 + hh]);
                    mma_f16(c1[i][j], a[i], b1[j2][hh], b1[j2][2 + hh]);
                }
            }
        }
    }

    #pragma unroll
    for (int i = 0; i < 2; i++) {
        #pragma unroll
        for (int h = 0; h < 2; h++) {
            int m = bm * 128 + wm * 32 + i * 16 + (lane >> 2) + h * 8;
            size_t orow = (size_t)m * DIM_D;
            #pragma unroll
            for (int j = 0; j < 4; j++) {
                int n = bn * 128 + wn * 32 + j * 8 + (lane & 3) * 2;
                float2 o0 = make_float2(c0[i][j][h * 2 + 0] * 16.0f,
                                        c0[i][j][h * 2 + 1] * 16.0f);
                float2 o1 = make_float2(c1[i][j][h * 2 + 0] * 16.0f,
                                        c1[i][j][h * 2 + 1] * 16.0f);
                *reinterpret_cast<float2*>(out + orow + n) = o0;
                *reinterpret_cast<float2*>(out + orow + n + 64) = o1;
            }
        }
    }
}

// ---------------- launch ------------------------------------------------------
extern "C" void kernel_launch(void* const* d_in, const int* in_sizes, int n_in,
                              void* d_out, int out_size) {
    const float* x  = (const float*)d_in[0];
    const float* Wg = (const float*)d_in[1];
    const float* Wu = (const float*)d_in[2];
    const float* Wd = (const float*)d_in[3];
    float* out = (float*)d_out;

    cudaFuncSetAttribute(gemm1_bf, cudaFuncAttributeMaxDynamicSharedMemorySize, G1_SMEM);
    cudaFuncSetAttribute(gemm3_f16, cudaFuncAttributeMaxDynamicSharedMemorySize, G3_SMEM);

    quant_kernel<<<DIM_M, 256>>>(x);

    const int n4 = DIM_H * DIM_D / 4;  // 4194304
    sign_fused_kernel<<<3 * n4 / 256, 256>>>((const float4*)Wg, (const float4*)Wu,
                                             (const float4*)Wd, n4);

    dim3 g1(DIM_H / 64, DIM_M / 128);    // (128, 64)
    gemm1_bf<<<g1, 256, G1_SMEM>>>();

    dim3 g3(DIM_D / 128, DIM_M / 128);   // (16, 64)
    gemm3_f16<<<g3, 256, G3_SMEM>>>(out);
}

// round 8
// speedup vs baseline: 3.1079x; 1.0244x over previous
#include <cuda_runtime.h>
#include <cuda_bf16.h>
#include <cuda_fp16.h>
#include <cstdint>

#define DIM_M 8192   // B*S
#define DIM_D 2048
#define DIM_H 8192

// ---------------- scratch (static device globals; no allocation) -------------
__device__ __nv_bfloat16 g_xq[(size_t)DIM_M * DIM_D];     // integer-valued quantized activations (bf16)
__device__ float         g_scale[DIM_M];                  // amax/127 per row
__device__ __nv_bfloat16 g_wg[(size_t)DIM_H * DIM_D];     // sign(W_g) bf16
__device__ __nv_bfloat16 g_wu[(size_t)DIM_H * DIM_D];     // sign(W_u) bf16
__device__ __half        g_wd[(size_t)DIM_D * DIM_H];     // sign(W_d) fp16
__device__ __half        g_p[(size_t)DIM_M * DIM_H];      // p * 2^-4, fp16

// ---------------- PTX helpers -------------------------------------------------
__device__ __forceinline__ uint32_t smem_u32(const void* p) {
    uint32_t a;
    asm("{ .reg .u64 t; cvta.to.shared.u64 t, %1; cvt.u32.u64 %0, t; }" : "=r"(a) : "l"(p));
    return a;
}
__device__ __forceinline__ void cp_async16(uint32_t smem, const void* gmem) {
    asm volatile("cp.async.cg.shared.global [%0], [%1], 16;\n" :: "r"(smem), "l"(gmem));
}
__device__ __forceinline__ void cp_commit() { asm volatile("cp.async.commit_group;\n"); }
template<int N> __device__ __forceinline__ void cp_wait_group() {
    asm volatile("cp.async.wait_group %0;\n" :: "n"(N));
}
__device__ __forceinline__ void ldm4(uint32_t* r, uint32_t addr) {
    asm volatile("ldmatrix.sync.aligned.m8n8.x4.shared.b16 {%0,%1,%2,%3}, [%4];"
                 : "=r"(r[0]), "=r"(r[1]), "=r"(r[2]), "=r"(r[3]) : "r"(addr));
}
__device__ __forceinline__ void mma_bf16(float* d, const uint32_t* a, uint32_t b0, uint32_t b1) {
    asm volatile(
        "mma.sync.aligned.m16n8k16.row.col.f32.bf16.bf16.f32 "
        "{%0,%1,%2,%3}, {%4,%5,%6,%7}, {%8,%9}, {%0,%1,%2,%3};\n"
        : "+f"(d[0]), "+f"(d[1]), "+f"(d[2]), "+f"(d[3])
        : "r"(a[0]), "r"(a[1]), "r"(a[2]), "r"(a[3]), "r"(b0), "r"(b1));
}
__device__ __forceinline__ void mma_f16(float* d, const uint32_t* a, uint32_t b0, uint32_t b1) {
    asm volatile(
        "mma.sync.aligned.m16n8k16.row.col.f32.f16.f16.f32 "
        "{%0,%1,%2,%3}, {%4,%5,%6,%7}, {%8,%9}, {%0,%1,%2,%3};\n"
        : "+f"(d[0]), "+f"(d[1]), "+f"(d[2]), "+f"(d[3])
        : "r"(a[0]), "r"(a[1]), "r"(a[2]), "r"(a[3]), "r"(b0), "r"(b1));
}

// ---------------- misc math ---------------------------------------------------
__device__ __forceinline__ float siluf(float x) { return x / (1.0f + expf(-x)); }

__device__ __forceinline__ float block_reduce(float v, float* sm, bool ismax) {
    int lane = threadIdx.x & 31, wid = threadIdx.x >> 5;
    #pragma unroll
    for (int o = 16; o; o >>= 1) {
        float t = __shfl_xor_sync(0xffffffffu, v, o);
        v = ismax ? fmaxf(v, t) : v + t;
    }
    if (lane == 0) sm[wid] = v;
    __syncthreads();
    float out = sm[0];
    #pragma unroll
    for (int i = 1; i < 8; i++) out = ismax ? fmaxf(out, sm[i]) : out + sm[i];
    __syncthreads();
    return out;
}

// ---------------- kernel 1: layernorm + activation quant (bf16 ints) ----------
__global__ __launch_bounds__(256) void quant_kernel(const float* __restrict__ x) {
    const int row = blockIdx.x, tid = threadIdx.x;
    const float4* xr = reinterpret_cast<const float4*>(x + (size_t)row * DIM_D);
    float4 a = xr[2 * tid], b = xr[2 * tid + 1];
    float v[8] = {a.x, a.y, a.z, a.w, b.x, b.y, b.z, b.w};

    __shared__ float sred[8];

    float s = 0.f;
    #pragma unroll
    for (int i = 0; i < 8; i++) s += v[i];
    s = block_reduce(s, sred, false);
    float mean = s * (1.0f / DIM_D);

    float q = 0.f;
    #pragma unroll
    for (int i = 0; i < 8; i++) { float d = v[i] - mean; q += d * d; }
    q = block_reduce(q, sred, false);
    float rstd = rsqrtf(q * (1.0f / DIM_D) + 1e-8f);

    float amax = 0.f;
    #pragma unroll
    for (int i = 0; i < 8; i++) amax = fmaxf(amax, fabsf((v[i] - mean) * rstd));
    amax = block_reduce(amax, sred, true);

    float sq = (amax > 0.f) ? (127.0f / amax) : 0.0f;

    uint32_t packed[4];
    #pragma unroll
    for (int i = 0; i < 4; i++) {
        float t0 = rintf((v[2 * i] - mean) * rstd * sq);
        float t1 = rintf((v[2 * i + 1] - mean) * rstd * sq);
        t0 = fminf(fmaxf(t0, -128.f), 127.f);
        t1 = fminf(fmaxf(t1, -128.f), 127.f);
        uint32_t lo = (uint32_t)__bfloat16_as_ushort(__float2bfloat16(t0));
        uint32_t hi = (uint32_t)__bfloat16_as_ushort(__float2bfloat16(t1));
        packed[i] = lo | (hi << 16);
    }
    reinterpret_cast<uint4*>(g_xq + (size_t)row * DIM_D)[tid] =
        make_uint4(packed[0], packed[1], packed[2], packed[3]);

    if (tid == 0) g_scale[row] = amax * (1.0f / 127.0f);
}

// ---------------- kernel 2: fused sign conversion (Wg,Wu -> bf16; Wd -> fp16) --
__global__ __launch_bounds__(256) void sign_fused_kernel(
        const float4* __restrict__ wg, const float4* __restrict__ wu,
        const float4* __restrict__ wd, int n4) {
    int gi = blockIdx.x * 256 + threadIdx.x;
    int which = gi / n4;          // 0: Wg, 1: Wu, 2: Wd
    int i = gi - which * n4;
    if (which < 2) {
        const float4 v = (which == 0) ? wg[i] : wu[i];
        __nv_bfloat16* o = (which == 0) ? g_wg : g_wu;
        float f0 = (v.x > 0.f) ? 1.f : ((v.x < 0.f) ? -1.f : 0.f);
        float f1 = (v.y > 0.f) ? 1.f : ((v.y < 0.f) ? -1.f : 0.f);
        float f2 = (v.z > 0.f) ? 1.f : ((v.z < 0.f) ? -1.f : 0.f);
        float f3 = (v.w > 0.f) ? 1.f : ((v.w < 0.f) ? -1.f : 0.f);
        uint32_t a0 = (uint32_t)__bfloat16_as_ushort(__float2bfloat16(f0));
        uint32_t a1 = (uint32_t)__bfloat16_as_ushort(__float2bfloat16(f1));
        uint32_t a2 = (uint32_t)__bfloat16_as_ushort(__float2bfloat16(f2));
        uint32_t a3 = (uint32_t)__bfloat16_as_ushort(__float2bfloat16(f3));
        uint2 out;
        out.x = a0 | (a1 << 16);
        out.y = a2 | (a3 << 16);
        reinterpret_cast<uint2*>(o)[i] = out;
    } else {
        const float4 v = wd[i];
        float f0 = (v.x > 0.f) ? 1.f : ((v.x < 0.f) ? -1.f : 0.f);
        float f1 = (v.y > 0.f) ? 1.f : ((v.y < 0.f) ? -1.f : 0.f);
        float f2 = (v.z > 0.f) ? 1.f : ((v.z < 0.f) ? -1.f : 0.f);
        float f3 = (v.w > 0.f) ? 1.f : ((v.w < 0.f) ? -1.f : 0.f);
        __half2 h0 = __floats2half2_rn(f0, f1);
        __half2 h1 = __floats2half2_rn(f2, f3);
        uint2 out;
        out.x = *reinterpret_cast<uint32_t*>(&h0);
        out.y = *reinterpret_cast<uint32_t*>(&h1);
        reinterpret_cast<uint2*>(g_wd)[i] = out;
    }
}

extern __shared__ __align__(128) char dsm[];

// =============================================================================
// GEMM1 (bf16): per CTA M=128, N=64(g)+64(u), BK=64. 2-stage pipeline,
// 2 CTAs/SM, single __syncthreads per iteration.
// smem stage (144B rows): A[128x144] @0, Bg[64x144] @18432, Bu @27648 (36864/st)
// =============================================================================
#define G1_STAGE 36864
#define G1_SMEM  (2 * G1_STAGE)

__global__ __launch_bounds__(256, 2) void gemm1_bf() {
    const int tid = threadIdx.x, warp = tid >> 5, lane = tid & 31;
    const int bn = blockIdx.x, bm = blockIdx.y;
    const int wm = warp & 3, wn = warp >> 2;
    uint32_t sb = smem_u32(dsm);

    const __nv_bfloat16* Ag = g_xq + (size_t)bm * 128 * DIM_D;
    const __nv_bfloat16* Bg = g_wg + (size_t)bn * 64 * DIM_D;
    const __nv_bfloat16* Bu = g_wu + (size_t)bn * 64 * DIM_D;

    float cg[2][4][4], cu[2][4][4];
    #pragma unroll
    for (int i = 0; i < 2; i++)
        #pragma unroll
        for (int j = 0; j < 4; j++)
            #pragma unroll
            for (int e = 0; e < 4; e++) { cg[i][j][e] = 0.f; cu[i][j][e] = 0.f; }

    auto load = [&](int st, int kt) {
        int k0 = kt * 64;
        uint32_t base = sb + st * G1_STAGE;
        #pragma unroll
        for (int it = 0; it < 4; it++) {
            int ch = tid + it * 256;
            int row = ch >> 3, seg = ch & 7;
            cp_async16(base + row * 144 + seg * 16,
                       Ag + (size_t)row * DIM_D + k0 + seg * 8);
        }
        #pragma unroll
        for (int it = 0; it < 2; it++) {
            int ch = tid + it * 256;
            int row = ch >> 3, seg = ch & 7;
            uint32_t d = row * 144 + seg * 16;
            size_t gofs = (size_t)row * DIM_D + k0 + seg * 8;
            cp_async16(base + 18432 + d, Bg + gofs);
            cp_async16(base + 27648 + d, Bu + gofs);
        }
        cp_commit();
    };

    load(0, 0);

    const int NCHUNK = DIM_D / 64;  // 32
    const uint32_t lrow = (lane & 15), lseg = (lane >> 4) << 4;

    for (int kt = 0; kt < NCHUNK; kt++) {
        int st = kt & 1;
        cp_wait_group<0>();
        __syncthreads();
        if (kt + 1 < NCHUNK) load(st ^ 1, kt + 1);
        uint32_t base = sb + st * G1_STAGE;
        #pragma unroll
        for (int kk = 0; kk < 4; kk++) {
            uint32_t koff = kk * 32 + lseg;
            uint32_t a[2][4], bg[2][4], bu[2][4];
            #pragma unroll
            for (int i = 0; i < 2; i++)
                ldm4(a[i], base + (wm * 32 + i * 16 + lrow) * 144 + koff);
            #pragma unroll
            for (int j2 = 0; j2 < 2; j2++) {
                uint32_t rb = (wn * 32 + j2 * 16 + lrow) * 144 + koff;
                ldm4(bg[j2], base + 18432 + rb);
                ldm4(bu[j2], base + 27648 + rb);
            }
            #pragma unroll
            for (int j = 0; j < 4; j++) {
                int j2 = j >> 1, hh = j & 1;
                #pragma unroll
                for (int i = 0; i < 2; i++) {
                    mma_bf16(cg[i][j], a[i], bg[j2][hh], bg[j2][2 + hh]);
                    mma_bf16(cu[i][j], a[i], bu[j2][hh], bu[j2][2 + hh]);
                }
            }
        }
    }

    // epilogue: scale, silu, product, *2^-4, fp16 store
    #pragma unroll
    for (int i = 0; i < 2; i++) {
        #pragma unroll
        for (int h = 0; h < 2; h++) {
            int m = bm * 128 + wm * 32 + i * 16 + (lane >> 2) + h * 8;
            float s = g_scale[m];
            size_t orow = (size_t)m * DIM_H;
            #pragma unroll
            for (int j = 0; j < 4; j++) {
                int n = bn * 64 + wn * 32 + j * 8 + (lane & 3) * 2;
                float g0 = cg[i][j][h * 2 + 0] * s;
                float g1 = cg[i][j][h * 2 + 1] * s;
                float u0 = cu[i][j][h * 2 + 0] * s;
                float u1 = cu[i][j][h * 2 + 1] * s;
                float p0 = siluf(g0) * u0 * 0.0625f;
                float p1 = siluf(g1) * u1 * 0.0625f;
                __half2 hp = __floats2half2_rn(p0, p1);
                *reinterpret_cast<uint32_t*>(g_p + orow + n) =
                    *reinterpret_cast<uint32_t*>(&hp);
            }
        }
    }
}

// =============================================================================
// GEMM3 (fp16): out[M,D] = 16 * (p16 @ sign(Wd)^T). CTA M=128, N=128 (two
// 64-col halves sharing A fragments). BK=64, 2-stage, 2 CTAs/SM, 1 sync/iter.
// smem stage (144B rows): A[128x144] @0, B0[64x144] @18432, B1 @27648 (36864/st)
// =============================================================================
#define G3_STAGE 36864
#define G3_SMEM  (2 * G3_STAGE)

__global__ __launch_bounds__(256, 2) void gemm3_f16(float* __restrict__ out) {
    const int tid = threadIdx.x, warp = tid >> 5, lane = tid & 31;
    const int bn = blockIdx.x, bm = blockIdx.y;
    const int wm = warp & 3, wn = warp >> 2;
    uint32_t sb = smem_u32(dsm);

    const __half* Ap = g_p  + (size_t)bm * 128 * DIM_H;
    const __half* B0 = g_wd + (size_t)bn * 128 * DIM_H;            // rows [0,64)
    const __half* B1 = B0 + (size_t)64 * DIM_H;                    // rows [64,128)

    float c0[2][4][4], c1[2][4][4];
    #pragma unroll
    for (int i = 0; i < 2; i++)
        #pragma unroll
        for (int j = 0; j < 4; j++)
            #pragma unroll
            for (int e = 0; e < 4; e++) { c0[i][j][e] = 0.f; c1[i][j][e] = 0.f; }

    auto load = [&](int st, int kt) {
        int k0 = kt * 64;
        uint32_t base = sb + st * G3_STAGE;
        #pragma unroll
        for (int it = 0; it < 4; it++) {
            int ch = tid + it * 256;
            int row = ch >> 3, seg = ch & 7;
            cp_async16(base + row * 144 + seg * 16,
                       Ap + (size_t)row * DIM_H + k0 + seg * 8);
        }
        #pragma unroll
        for (int it = 0; it < 2; it++) {
            int ch = tid + it * 256;
            int row = ch >> 3, seg = ch & 7;
            uint32_t d = row * 144 + seg * 16;
            size_t gofs = (size_t)row * DIM_H + k0 + seg * 8;
            cp_async16(base + 18432 + d, B0 + gofs);
            cp_async16(base + 27648 + d, B1 + gofs);
        }
        cp_commit();
    };

    load(0, 0);

    const int NCHUNK = DIM_H / 64;  // 128
    const uint32_t lrow = (lane & 15), lseg = (lane >> 4) << 4;

    for (int kt = 0; kt < NCHUNK; kt++) {
        int st = kt & 1;
        cp_wait_group<0>();
        __syncthreads();
        if (kt + 1 < NCHUNK) load(st ^ 1, kt + 1);
        uint32_t base = sb + st * G3_STAGE;
        #pragma unroll
        for (int kk = 0; kk < 4; kk++) {
            uint32_t koff = kk * 32 + lseg;
            uint32_t a[2][4], b0[2][4], b1[2][4];
            #pragma unroll
            for (int i = 0; i < 2; i++)
                ldm4(a[i], base + (wm * 32 + i * 16 + lrow) * 144 + koff);
            #pragma unroll
            for (int j2 = 0; j2 < 2; j2++) {
                uint32_t rb = (wn * 32 + j2 * 16 + lrow) * 144 + koff;
                ldm4(b0[j2], base + 18432 + rb);
                ldm4(b1[j2], base + 27648 + rb);
            }
            #pragma unroll
            for (int j = 0; j < 4; j++) {
                int j2 = j >> 1, hh = j & 1;
                #pragma unroll
                for (int i = 0; i < 2; i++) {
                    mma_f16(c0[i][j], a[i], b0[j2][hh], b0[j2][2 + hh]);
                    mma_f16(c1[i][j], a[i], b1[j2][hh], b1[j2][2 + hh]);
                }
            }
        }
    }

    #pragma unroll
    for (int i = 0; i < 2; i++) {
        #pragma unroll
        for (int h = 0; h < 2; h++) {
            int m = bm * 128 + wm * 32 + i * 16 + (lane >> 2) + h * 8;
            size_t orow = (size_t)m * DIM_D;
            #pragma unroll
            for (int j = 0; j < 4; j++) {
                int n = bn * 128 + wn * 32 + j * 8 + (lane & 3) * 2;
                float2 o0 = make_float2(c0[i][j][h * 2 + 0] * 16.0f,
                                        c0[i][j][h * 2 + 1] * 16.0f);
                float2 o1 = make_float2(c1[i][j][h * 2 + 0] * 16.0f,
                                        c1[i][j][h * 2 + 1] * 16.0f);
                *reinterpret_cast<float2*>(out + orow + n) = o0;
                *reinterpret_cast<float2*>(out + orow + n + 64) = o1;
            }
        }
    }
}

// ---------------- launch ------------------------------------------------------
extern "C" void kernel_launch(void* const* d_in, const int* in_sizes, int n_in,
                              void* d_out, int out_size) {
    const float* x  = (const float*)d_in[0];
    const float* Wg = (const float*)d_in[1];
    const float* Wu = (const float*)d_in[2];
    const float* Wd = (const float*)d_in[3];
    float* out = (float*)d_out;

    cudaFuncSetAttribute(gemm1_bf, cudaFuncAttributeMaxDynamicSharedMemorySize, G1_SMEM);
    cudaFuncSetAttribute(gemm3_f16, cudaFuncAttributeMaxDynamicSharedMemorySize, G3_SMEM);

    quant_kernel<<<DIM_M, 256>>>(x);

    const int n4 = DIM_H * DIM_D / 4;  // 4194304
    sign_fused_kernel<<<3 * n4 / 256, 256>>>((const float4*)Wg, (const float4*)Wu,
                                             (const float4*)Wd, n4);

    dim3 g1(DIM_H / 64, DIM_M / 128);    // (128, 64)
    gemm1_bf<<<g1, 256, G1_SMEM>>>();

    dim3 g3(DIM_D / 128, DIM_M / 128);   // (16, 64)
    gemm3_f16<<<g3, 256, G3_SMEM>>>(out);
}